// round 9
// baseline (speedup 1.0000x reference)
#include <cuda_runtime.h>
#include <cstdint>

#define T_STEPS 512
#define BSZ     64
#define NIN     1024
#define HID     1024
#define NOUT    1024

// recurrence partition
#define NC       8
#define KC       128
#define JT       64
#define RNN_BLOCKS 128
#define SHS      132          // padded smem row stride (floats), scan

// scratch
__device__ float   g_UH[(size_t)T_STEPS * BSZ * HID];     // U (input contributions)
__device__ float   g_HThi[(size_t)T_STEPS * BSZ * HID];   // tf32-hi of h_t, all t
__device__ float   g_HTlo[(size_t)T_STEPS * BSZ * HID];   // tf32-lo of h_t, all t
__device__ float   g_xhi[(size_t)T_STEPS * BSZ * NIN];
__device__ float   g_xlo[(size_t)T_STEPS * BSZ * NIN];
__device__ float   g_Wxhi[HID * NIN];
__device__ float   g_Wxlo[HID * NIN];
__device__ float   g_Wohi[NOUT * HID];
__device__ float   g_Wolo[NOUT * HID];
__device__ float   g_part[NC * BSZ * HID];
__device__ unsigned g_flags[RNN_BLOCKS];   // zero-init; reset to 0 at scan end
__device__ unsigned g_cnt;
__device__ unsigned g_gen;

// ===========================================================================
// common helpers
// ===========================================================================
__device__ __forceinline__ void cp_async16(uint32_t smem_addr, const void* gptr) {
    asm volatile("cp.async.cg.shared.global [%0], [%1], 16;"
                 :: "r"(smem_addr), "l"(gptr));
}
__device__ __forceinline__ uint32_t smem_u32(const void* p) {
    uint32_t a;
    asm("{ .reg .u64 t; cvta.to.shared.u64 t, %1; cvt.u32.u64 %0, t; }"
        : "=r"(a) : "l"(p));
    return a;
}
__device__ __forceinline__ uint32_t f2tf32(float v) {
    uint32_t r;
    asm("cvt.rna.tf32.f32 %0, %1;" : "=r"(r) : "f"(v));
    return r;
}
__device__ __forceinline__ void tf32_split(float x, uint32_t& hi, uint32_t& lo) {
    hi = f2tf32(x);
    lo = f2tf32(x - __uint_as_float(hi));
}
__device__ __forceinline__ void mma_tf32(
    float& d0, float& d1, float& d2, float& d3,
    uint32_t a0, uint32_t a1, uint32_t a2, uint32_t a3,
    uint32_t b0, uint32_t b1)
{
    asm volatile(
        "mma.sync.aligned.m16n8k8.row.col.f32.tf32.tf32.f32 "
        "{%0,%1,%2,%3}, {%4,%5,%6,%7}, {%8,%9}, {%0,%1,%2,%3};"
        : "+f"(d0), "+f"(d1), "+f"(d2), "+f"(d3)
        : "r"(a0), "r"(a1), "r"(a2), "r"(a3), "r"(b0), "r"(b1));
}

// ===========================================================================
// prep: hi/lo split kernels
// ===========================================================================
__device__ __forceinline__ void split4(float4 v, float4& hv, float4& lv) {
    uint32_t h, l;
    tf32_split(v.x, h, l); hv.x = __uint_as_float(h); lv.x = __uint_as_float(l);
    tf32_split(v.y, h, l); hv.y = __uint_as_float(h); lv.y = __uint_as_float(l);
    tf32_split(v.z, h, l); hv.z = __uint_as_float(h); lv.z = __uint_as_float(l);
    tf32_split(v.w, h, l); hv.w = __uint_as_float(h); lv.w = __uint_as_float(l);
}

__global__ void split_plain_k(const float* __restrict__ src,
                              float* __restrict__ hi, float* __restrict__ lo, int n4)
{
    int i = blockIdx.x * blockDim.x + threadIdx.x;
    if (i >= n4) return;
    float4 hv, lv;
    split4(reinterpret_cast<const float4*>(src)[i], hv, lv);
    reinterpret_cast<float4*>(hi)[i] = hv;
    reinterpret_cast<float4*>(lo)[i] = lv;
}

__global__ void split_strided_k(const float* __restrict__ src, int srcld, int cols,
                                float* __restrict__ hi, float* __restrict__ lo, int n4)
{
    int i = blockIdx.x * blockDim.x + threadIdx.x;
    if (i >= n4) return;
    int e = i * 4;
    int r = e / cols;
    int c0 = e - r * cols;
    float4 hv, lv;
    float4 v = *reinterpret_cast<const float4*>(src + (size_t)r * srcld + c0);
    split4(v, hv, lv);
    reinterpret_cast<float4*>(hi)[i] = hv;
    reinterpret_cast<float4*>(lo)[i] = lv;
}

// ===========================================================================
// 3xTF32 GEMM on pre-split operands (launch_bounds(256,2): regs<=128)
// ===========================================================================
#define BM 128
#define BN 128
#define BK 16
#define SST 20
#define GTILE (BM * SST)
#define G_SMEM_PS (8 * GTILE * 4)   // 81920 bytes

__global__ __launch_bounds__(256, 2) void gemm_mma_ps(
    const float* __restrict__ Ahi, const float* __restrict__ Alo,
    const float* __restrict__ Whi, const float* __restrict__ Wlo,
    const float* __restrict__ bias,
    float* __restrict__ C, int ldc, int K)
{
    extern __shared__ float smp[];
    float* pAhi = smp;
    float* pAlo = smp + 2 * GTILE;
    float* pWhi = smp + 4 * GTILE;
    float* pWlo = smp + 6 * GTILE;

    const int tid = threadIdx.x;
    const int wid = tid >> 5;
    const int lane = tid & 31;
    const int m0 = blockIdx.y * BM;
    const int n0 = blockIdx.x * BN;

    const int warp_m = (wid >> 2) * 64;
    const int warp_n = (wid & 3) * 32;

    const int lrow = tid >> 1;
    const int lc   = (tid & 1) * 8;
    const float* gAh = Ahi + (size_t)(m0 + lrow) * K + lc;
    const float* gAl = Alo + (size_t)(m0 + lrow) * K + lc;
    const float* gWh = Whi + (size_t)(n0 + lrow) * K + lc;
    const float* gWl = Wlo + (size_t)(n0 + lrow) * K + lc;

    const uint32_t uAh = smem_u32(pAhi);
    const uint32_t uAl = smem_u32(pAlo);
    const uint32_t uWh = smem_u32(pWhi);
    const uint32_t uWl = smem_u32(pWlo);
    const uint32_t soff = (uint32_t)(lrow * SST + lc) * 4u;

    const int NK = K / BK;

    {
        cp_async16(uAh + soff,      gAh);  cp_async16(uAh + soff + 16, gAh + 4);
        cp_async16(uAl + soff,      gAl);  cp_async16(uAl + soff + 16, gAl + 4);
        cp_async16(uWh + soff,      gWh);  cp_async16(uWh + soff + 16, gWh + 4);
        cp_async16(uWl + soff,      gWl);  cp_async16(uWl + soff + 16, gWl + 4);
        asm volatile("cp.async.commit_group;");
    }

    float acc[4][4][4];
#pragma unroll
    for (int i = 0; i < 4; i++)
#pragma unroll
        for (int j = 0; j < 4; j++)
#pragma unroll
            for (int q = 0; q < 4; q++) acc[i][j][q] = 0.0f;

    const int fr = lane >> 2;
    const int fc = lane & 3;

    for (int it = 0; it < NK; it++) {
        const int buf = it & 1;

        if (it + 1 < NK) {
            const uint32_t d = ((it + 1) & 1) * (GTILE * 4);
            const int ko = (it + 1) * BK;
            cp_async16(uAh + d + soff,      gAh + ko);
            cp_async16(uAh + d + soff + 16, gAh + ko + 4);
            cp_async16(uAl + d + soff,      gAl + ko);
            cp_async16(uAl + d + soff + 16, gAl + ko + 4);
            cp_async16(uWh + d + soff,      gWh + ko);
            cp_async16(uWh + d + soff + 16, gWh + ko + 4);
            cp_async16(uWl + d + soff,      gWl + ko);
            cp_async16(uWl + d + soff + 16, gWl + ko + 4);
            asm volatile("cp.async.commit_group;");
            asm volatile("cp.async.wait_group 1;");
        } else {
            asm volatile("cp.async.wait_group 0;");
        }
        __syncthreads();

        const float* Abh = pAhi + buf * GTILE;
        const float* Abl = pAlo + buf * GTILE;
        const float* Wbh = pWhi + buf * GTILE;
        const float* Wbl = pWlo + buf * GTILE;

#pragma unroll
        for (int k8 = 0; k8 < 2; k8++) {
            const int kb = k8 * 8;

            uint32_t bh[4][2], bl[4][2];
#pragma unroll
            for (int j = 0; j < 4; j++) {
                const int nb = (warp_n + j * 8 + fr) * SST + kb + fc;
                bh[j][0] = __float_as_uint(Wbh[nb]);
                bh[j][1] = __float_as_uint(Wbh[nb + 4]);
                bl[j][0] = __float_as_uint(Wbl[nb]);
                bl[j][1] = __float_as_uint(Wbl[nb + 4]);
            }

#pragma unroll
            for (int i = 0; i < 4; i++) {
                const int r0 = (warp_m + i * 16 + fr) * SST + kb + fc;
                const int r8 = r0 + 8 * SST;
                uint32_t ah[4], al[4];
                ah[0] = __float_as_uint(Abh[r0]);
                ah[1] = __float_as_uint(Abh[r8]);
                ah[2] = __float_as_uint(Abh[r0 + 4]);
                ah[3] = __float_as_uint(Abh[r8 + 4]);
                al[0] = __float_as_uint(Abl[r0]);
                al[1] = __float_as_uint(Abl[r8]);
                al[2] = __float_as_uint(Abl[r0 + 4]);
                al[3] = __float_as_uint(Abl[r8 + 4]);

#pragma unroll
                for (int j = 0; j < 4; j++) {
                    mma_tf32(acc[i][j][0], acc[i][j][1], acc[i][j][2], acc[i][j][3],
                             ah[0], ah[1], ah[2], ah[3], bh[j][0], bh[j][1]);
                    mma_tf32(acc[i][j][0], acc[i][j][1], acc[i][j][2], acc[i][j][3],
                             ah[0], ah[1], ah[2], ah[3], bl[j][0], bl[j][1]);
                    mma_tf32(acc[i][j][0], acc[i][j][1], acc[i][j][2], acc[i][j][3],
                             al[0], al[1], al[2], al[3], bh[j][0], bh[j][1]);
                }
            }
        }
        __syncthreads();
    }

#pragma unroll
    for (int j = 0; j < 4; j++) {
        const int ncol = n0 + warp_n + j * 8 + fc * 2;
        const float2 bv = *reinterpret_cast<const float2*>(&bias[ncol]);
#pragma unroll
        for (int i = 0; i < 4; i++) {
            const int r0 = m0 + warp_m + i * 16 + fr;
            float2 v0, v1;
            v0.x = acc[i][j][0] + bv.x; v0.y = acc[i][j][1] + bv.y;
            v1.x = acc[i][j][2] + bv.x; v1.y = acc[i][j][3] + bv.y;
            *reinterpret_cast<float2*>(&C[(size_t)r0 * ldc + ncol])       = v0;
            *reinterpret_cast<float2*>(&C[(size_t)(r0 + 8) * ldc + ncol]) = v1;
        }
    }
}

// ===========================================================================
// Flag-array grid barrier: one release-store per block (own flag),
// 128 threads poll 128 distinct flags. No atomic contention.
// seq must be monotonically increasing within the kernel; flags reset at end.
// ===========================================================================
__device__ __forceinline__ void grid_barrier_flags(unsigned seq)
{
    __syncthreads();
    if (threadIdx.x == 0) {
        asm volatile("st.release.gpu.global.u32 [%0], %1;"
                     :: "l"(&g_flags[blockIdx.x]), "r"(seq));
    }
    if (threadIdx.x < RNN_BLOCKS) {
        unsigned v;
        do {
            asm volatile("ld.acquire.gpu.global.u32 %0, [%1];"
                         : "=r"(v) : "l"(&g_flags[threadIdx.x]));
        } while (v < seq);
    }
    __syncthreads();
}

// legacy atomic barrier (used once at scan end for the flag reset)
__device__ __forceinline__ void grid_barrier_atomic()
{
    __syncthreads();
    if (threadIdx.x == 0) {
        unsigned gen;
        asm volatile("ld.acquire.gpu.global.u32 %0, [%1];"
                     : "=r"(gen) : "l"(&g_gen));
        unsigned old;
        asm volatile("atom.acq_rel.gpu.global.add.u32 %0, [%1], 1;"
                     : "=r"(old) : "l"(&g_cnt));
        if (old == gridDim.x - 1) {
            asm volatile("st.relaxed.gpu.global.u32 [%0], 0;"
                         :: "l"(&g_cnt));
            asm volatile("red.release.gpu.global.add.u32 [%0], 1;"
                         :: "l"(&g_gen));
        } else {
            unsigned cur;
            do {
                asm volatile("ld.acquire.gpu.global.u32 %0, [%1];"
                             : "=r"(cur) : "l"(&g_gen));
            } while (cur == gen);
        }
    }
    __syncthreads();
}

// ===========================================================================
// Persistent recurrence (tensor-core Phase A; flag barriers)
// ===========================================================================
__global__ __launch_bounds__(256) void rnn_scan_k(
    const float* __restrict__ h0, const float* __restrict__ Wi2h)
{
    extern __shared__ float sm[];
    float* sh_hi = sm;                 // [64][SHS]
    float* sh_lo = sm + 64 * SHS;      // [64][SHS]
    const uint32_t u_hi = smem_u32(sh_hi);
    const uint32_t u_lo = smem_u32(sh_lo);

    const int tid = threadIdx.x;
    const int bid = blockIdx.x;
    const int wid = tid >> 5;
    const int lane = tid & 31;
    const int c   = bid >> 4;
    const int jt  = bid & 15;
    const int j0  = jt * JT;
    const int k0  = c * KC;

    const int mh = wid >> 2;
    const int nw = wid & 3;
    const int fr = lane >> 2;
    const int fc = lane & 3;

    // preload W fragments (loop-invariant)
    uint32_t Wh[2][16][2], Wl[2][16][2];
#pragma unroll
    for (int nj = 0; nj < 2; nj++) {
        const int n = j0 + nw * 16 + nj * 8 + fr;
        const float* wr = &Wi2h[(size_t)n * (NIN + HID) + NIN + k0];
#pragma unroll
        for (int ks = 0; ks < 16; ks++) {
            tf32_split(wr[ks * 8 + fc],     Wh[nj][ks][0], Wl[nj][ks][0]);
            tf32_split(wr[ks * 8 + fc + 4], Wh[nj][ks][1], Wl[nj][ks][1]);
        }
    }

    // Phase B ownership: 512 elements, 2 consecutive per thread
    const int pb_flat = bid * 512 + 2 * tid;
    const int pb_b = pb_flat >> 10;
    const int pb_j = pb_flat & (HID - 1);

    for (int t = 0; t < T_STEPS; t++) {
        // --- stage h(t-1) chunk into smem (split form) ---
        if (t == 0) {
#pragma unroll
            for (int p = 0; p < 8; p++) {
                const int idx4 = tid + p * 256;
                const int b = idx4 >> 5;
                const int kg = (idx4 & 31) * 4;
                float4 v = *reinterpret_cast<const float4*>(&h0[b * HID + k0 + kg]);
                float4 hv, lv;
                split4(v, hv, lv);
                *reinterpret_cast<float4*>(&sh_hi[b * SHS + kg]) = hv;
                *reinterpret_cast<float4*>(&sh_lo[b * SHS + kg]) = lv;
            }
        } else {
            const size_t tb = (size_t)(t - 1) * BSZ * HID;
#pragma unroll
            for (int p = 0; p < 8; p++) {
                const int idx4 = tid + p * 256;
                const int b = idx4 >> 5;
                const int kg = (idx4 & 31) * 4;
                const size_t src = tb + b * HID + k0 + kg;
                const uint32_t dofs = (uint32_t)(b * SHS + kg) * 4u;
                cp_async16(u_hi + dofs, &g_HThi[src]);
                cp_async16(u_lo + dofs, &g_HTlo[src]);
            }
            asm volatile("cp.async.commit_group;");
            asm volatile("cp.async.wait_group 0;");
        }
        __syncthreads();

        // --- Phase A: 3xTF32 mma over 16 k8 steps ---
        float acc[2][2][4];
#pragma unroll
        for (int mi = 0; mi < 2; mi++)
#pragma unroll
            for (int nj = 0; nj < 2; nj++)
#pragma unroll
                for (int q = 0; q < 4; q++) acc[mi][nj][q] = 0.0f;

#pragma unroll
        for (int ks = 0; ks < 16; ks++) {
            const int kk = ks * 8 + fc;
            uint32_t ahi[2][4], alo[2][4];
#pragma unroll
            for (int mi = 0; mi < 2; mi++) {
                const int r0 = (mh * 32 + mi * 16 + fr) * SHS;
                const int r8 = r0 + 8 * SHS;
                ahi[mi][0] = __float_as_uint(sh_hi[r0 + kk]);
                ahi[mi][1] = __float_as_uint(sh_hi[r8 + kk]);
                ahi[mi][2] = __float_as_uint(sh_hi[r0 + kk + 4]);
                ahi[mi][3] = __float_as_uint(sh_hi[r8 + kk + 4]);
                alo[mi][0] = __float_as_uint(sh_lo[r0 + kk]);
                alo[mi][1] = __float_as_uint(sh_lo[r8 + kk]);
                alo[mi][2] = __float_as_uint(sh_lo[r0 + kk + 4]);
                alo[mi][3] = __float_as_uint(sh_lo[r8 + kk + 4]);
            }
#pragma unroll
            for (int mi = 0; mi < 2; mi++)
#pragma unroll
                for (int nj = 0; nj < 2; nj++) {
                    mma_tf32(acc[mi][nj][0], acc[mi][nj][1], acc[mi][nj][2], acc[mi][nj][3],
                             ahi[mi][0], ahi[mi][1], ahi[mi][2], ahi[mi][3],
                             Wh[nj][ks][0], Wh[nj][ks][1]);
                    mma_tf32(acc[mi][nj][0], acc[mi][nj][1], acc[mi][nj][2], acc[mi][nj][3],
                             ahi[mi][0], ahi[mi][1], ahi[mi][2], ahi[mi][3],
                             Wl[nj][ks][0], Wl[nj][ks][1]);
                    mma_tf32(acc[mi][nj][0], acc[mi][nj][1], acc[mi][nj][2], acc[mi][nj][3],
                             alo[mi][0], alo[mi][1], alo[mi][2], alo[mi][3],
                             Wh[nj][ks][0], Wh[nj][ks][1]);
                }
        }

        // --- write partials ---
#pragma unroll
        for (int mi = 0; mi < 2; mi++) {
            const int b0 = mh * 32 + mi * 16 + fr;
#pragma unroll
            for (int nj = 0; nj < 2; nj++) {
                const int n = j0 + nw * 16 + nj * 8 + fc * 2;
                float2 v0, v1;
                v0.x = acc[mi][nj][0]; v0.y = acc[mi][nj][1];
                v1.x = acc[mi][nj][2]; v1.y = acc[mi][nj][3];
                __stcg(reinterpret_cast<float2*>(
                    &g_part[(size_t)(c * BSZ + b0) * HID + n]), v0);
                __stcg(reinterpret_cast<float2*>(
                    &g_part[(size_t)(c * BSZ + b0 + 8) * HID + n]), v1);
            }
        }

        // prefetch U (float2) before the barrier
        const size_t u0 = ((size_t)t * BSZ + pb_b) * HID + pb_j;
        float2 uv = __ldcg(reinterpret_cast<const float2*>(&g_UH[u0]));

        grid_barrier_flags(2 * t + 1);

        // --- Phase B: reduce + tanh, store split h(t) ---
        {
            float v0 = uv.x, v1 = uv.y;
#pragma unroll
            for (int cc = 0; cc < NC; cc++) {
                float2 p = __ldcg(reinterpret_cast<const float2*>(
                    &g_part[(size_t)(cc * BSZ + pb_b) * HID + pb_j]));
                v0 += p.x;
                v1 += p.y;
            }
            v0 = tanhf(v0);
            v1 = tanhf(v1);
            uint32_t h0b, l0b, h1b, l1b;
            tf32_split(v0, h0b, l0b);
            tf32_split(v1, h1b, l1b);
            const size_t ho = (size_t)t * BSZ * HID + pb_flat;
            float2 hv, lv;
            hv.x = __uint_as_float(h0b); hv.y = __uint_as_float(h1b);
            lv.x = __uint_as_float(l0b); lv.y = __uint_as_float(l1b);
            __stcg(reinterpret_cast<float2*>(&g_HThi[ho]), hv);
            __stcg(reinterpret_cast<float2*>(&g_HTlo[ho]), lv);
        }

        grid_barrier_flags(2 * t + 2);
    }

    // reset flags for the next graph replay (behind an atomic barrier so no
    // block is still polling old flag values when they get zeroed)
    grid_barrier_atomic();
    if (tid == 0)
        asm volatile("st.relaxed.gpu.global.u32 [%0], 0;" :: "l"(&g_flags[bid]));
}

// ===========================================================================
extern "C" void kernel_launch(void* const* d_in, const int* in_sizes, int n_in,
                              void* d_out, int out_size)
{
    (void)in_sizes; (void)n_in; (void)out_size;
    const float* x     = (const float*)d_in[0];
    const float* h0    = (const float*)d_in[1];
    const float* W_i2h = (const float*)d_in[2];
    const float* b_i2h = (const float*)d_in[3];
    const float* W_h2o = (const float*)d_in[4];
    const float* b_h2o = (const float*)d_in[5];
    float* out = (float*)d_out;

    float *uh, *xhi, *xlo, *hthi, *htlo, *wxhi, *wxlo, *wohi, *wolo;
    cudaGetSymbolAddress((void**)&uh,   g_UH);
    cudaGetSymbolAddress((void**)&xhi,  g_xhi);
    cudaGetSymbolAddress((void**)&xlo,  g_xlo);
    cudaGetSymbolAddress((void**)&hthi, g_HThi);
    cudaGetSymbolAddress((void**)&htlo, g_HTlo);
    cudaGetSymbolAddress((void**)&wxhi, g_Wxhi);
    cudaGetSymbolAddress((void**)&wxlo, g_Wxlo);
    cudaGetSymbolAddress((void**)&wohi, g_Wohi);
    cudaGetSymbolAddress((void**)&wolo, g_Wolo);

    cudaFuncSetAttribute(gemm_mma_ps,
        cudaFuncAttributeMaxDynamicSharedMemorySize, G_SMEM_PS);

    // 0) prep: hi/lo splits
    {
        int n4x = (T_STEPS * BSZ * NIN) / 4;
        split_plain_k<<<(n4x + 255) / 256, 256>>>(x, xhi, xlo, n4x);
        int n4w = (HID * NIN) / 4;
        split_strided_k<<<(n4w + 255) / 256, 256>>>(W_i2h, NIN + HID, NIN,
                                                    wxhi, wxlo, n4w);
        int n4o = (NOUT * HID) / 4;
        split_plain_k<<<(n4o + 255) / 256, 256>>>(W_h2o, wohi, wolo, n4o);
    }

    // 1) U = X @ Wx^T + b_i2h
    dim3 g1(HID / BN, (T_STEPS * BSZ) / BM);
    gemm_mma_ps<<<g1, 256, G_SMEM_PS>>>(xhi, xlo, wxhi, wxlo, b_i2h,
                                        uh, HID, NIN);

    // 2) sequential recurrence
    int smem = 2 * 64 * SHS * (int)sizeof(float);
    cudaFuncSetAttribute(rnn_scan_k, cudaFuncAttributeMaxDynamicSharedMemorySize, smem);
    rnn_scan_k<<<RNN_BLOCKS, 256, smem>>>(h0, W_i2h);

    // 3) out = H @ Wo^T + b_h2o
    dim3 g3(NOUT / BN, (T_STEPS * BSZ) / BM);
    gemm_mma_ps<<<g3, 256, G_SMEM_PS>>>(hthi, htlo, wohi, wolo, b_h2o,
                                        out, NOUT, HID);
}

// round 10
// speedup vs baseline: 1.9105x; 1.9105x over previous
#include <cuda_runtime.h>
#include <cstdint>

#define T_STEPS 512
#define BSZ     64
#define NIN     1024
#define HID     1024
#define NOUT    1024

// recurrence partition
#define NC       8
#define KC       128
#define JT       64
#define RNN_BLOCKS 128
#define SHS      132          // padded smem row stride (floats)

// scratch
__device__ float   g_UH[(size_t)T_STEPS * BSZ * HID];   // U -> h_t (fp32)
__device__ float   g_Hhi[BSZ * HID];                    // tf32-hi of current h
__device__ float   g_Hlo[BSZ * HID];                    // tf32-lo of current h
__device__ float   g_part[NC * BSZ * HID];
__device__ unsigned g_flags[RNN_BLOCKS];   // zero-init; reset at scan end
__device__ unsigned g_gen;                 // broadcast word; reset at scan end
__device__ unsigned g_cnt;                 // legacy end barrier
__device__ unsigned g_gen2;                // legacy end barrier (monotonic ok)

// ===========================================================================
// common helpers
// ===========================================================================
__device__ __forceinline__ void cp_async16(uint32_t smem_addr, const void* gptr) {
    asm volatile("cp.async.cg.shared.global [%0], [%1], 16;"
                 :: "r"(smem_addr), "l"(gptr));
}
__device__ __forceinline__ uint32_t smem_u32(const void* p) {
    uint32_t a;
    asm("{ .reg .u64 t; cvta.to.shared.u64 t, %1; cvt.u32.u64 %0, t; }"
        : "=r"(a) : "l"(p));
    return a;
}
__device__ __forceinline__ uint32_t f2tf32(float v) {
    uint32_t r;
    asm("cvt.rna.tf32.f32 %0, %1;" : "=r"(r) : "f"(v));
    return r;
}
__device__ __forceinline__ void tf32_split(float x, uint32_t& hi, uint32_t& lo) {
    hi = f2tf32(x);
    lo = f2tf32(x - __uint_as_float(hi));
}
__device__ __forceinline__ void split4(float4 v, float4& hv, float4& lv) {
    uint32_t h, l;
    tf32_split(v.x, h, l); hv.x = __uint_as_float(h); lv.x = __uint_as_float(l);
    tf32_split(v.y, h, l); hv.y = __uint_as_float(h); lv.y = __uint_as_float(l);
    tf32_split(v.z, h, l); hv.z = __uint_as_float(h); lv.z = __uint_as_float(l);
    tf32_split(v.w, h, l); hv.w = __uint_as_float(h); lv.w = __uint_as_float(l);
}
__device__ __forceinline__ void mma_tf32(
    float& d0, float& d1, float& d2, float& d3,
    uint32_t a0, uint32_t a1, uint32_t a2, uint32_t a3,
    uint32_t b0, uint32_t b1)
{
    asm volatile(
        "mma.sync.aligned.m16n8k8.row.col.f32.tf32.tf32.f32 "
        "{%0,%1,%2,%3}, {%4,%5,%6,%7}, {%8,%9}, {%0,%1,%2,%3};"
        : "+f"(d0), "+f"(d1), "+f"(d2), "+f"(d3)
        : "r"(a0), "r"(a1), "r"(a2), "r"(a3), "r"(b0), "r"(b1));
}

// ===========================================================================
// 3xTF32 mma.sync GEMM (R5/R7 version — known good, ~1.07ms each)
// ===========================================================================
#define BM 128
#define BN 128
#define BK 16
#define SST 20

__global__ __launch_bounds__(256) void gemm_mma_k(
    const float* __restrict__ A, int lda,
    const float* __restrict__ Wm, int ldw,
    const float* __restrict__ bias,
    float* __restrict__ C, int ldc, int K)
{
    __shared__ float As[2][BM * SST];
    __shared__ float Ws[2][BN * SST];

    const int tid = threadIdx.x;
    const int wid = tid >> 5;
    const int lane = tid & 31;
    const int m0 = blockIdx.y * BM;
    const int n0 = blockIdx.x * BN;

    const int warp_m = (wid >> 2) * 64;
    const int warp_n = (wid & 3) * 32;

    const int lrow = tid >> 1;
    const int lc   = (tid & 1) * 8;
    const float* Ag = A  + (size_t)(m0 + lrow) * lda + lc;
    const float* Wg = Wm + (size_t)(n0 + lrow) * ldw + lc;
    const uint32_t sAs = smem_u32(&As[0][0]);
    const uint32_t sWs = smem_u32(&Ws[0][0]);
    const uint32_t soff = (uint32_t)(lrow * SST + lc) * 4u;

    const int NK = K / BK;

    {
        cp_async16(sAs + soff,      Ag);
        cp_async16(sAs + soff + 16, Ag + 4);
        cp_async16(sWs + soff,      Wg);
        cp_async16(sWs + soff + 16, Wg + 4);
        asm volatile("cp.async.commit_group;");
    }

    float acc[4][4][4];
#pragma unroll
    for (int i = 0; i < 4; i++)
#pragma unroll
        for (int j = 0; j < 4; j++)
#pragma unroll
            for (int q = 0; q < 4; q++) acc[i][j][q] = 0.0f;

    const int fr = lane >> 2;
    const int fc = lane & 3;

    for (int it = 0; it < NK; it++) {
        const int buf = it & 1;

        if (it + 1 < NK) {
            const uint32_t dst = (it + 1) & 1;
            const float* Ap = Ag + (size_t)(it + 1) * BK;
            const float* Wp = Wg + (size_t)(it + 1) * BK;
            cp_async16(sAs + dst * (BM * SST * 4) + soff,      Ap);
            cp_async16(sAs + dst * (BM * SST * 4) + soff + 16, Ap + 4);
            cp_async16(sWs + dst * (BN * SST * 4) + soff,      Wp);
            cp_async16(sWs + dst * (BN * SST * 4) + soff + 16, Wp + 4);
            asm volatile("cp.async.commit_group;");
            asm volatile("cp.async.wait_group 1;");
        } else {
            asm volatile("cp.async.wait_group 0;");
        }
        __syncthreads();

        const float* Ab = &As[buf][0];
        const float* Wb = &Ws[buf][0];

#pragma unroll
        for (int k8 = 0; k8 < 2; k8++) {
            const int kb = k8 * 8;

            uint32_t bh[4][2], bl[4][2];
#pragma unroll
            for (int j = 0; j < 4; j++) {
                const int nb = warp_n + j * 8;
                float b0 = Wb[(nb + fr) * SST + kb + fc];
                float b1 = Wb[(nb + fr) * SST + kb + fc + 4];
                tf32_split(b0, bh[j][0], bl[j][0]);
                tf32_split(b1, bh[j][1], bl[j][1]);
            }

#pragma unroll
            for (int i = 0; i < 4; i++) {
                const int mb = warp_m + i * 16;
                float a0 = Ab[(mb + fr)     * SST + kb + fc];
                float a1 = Ab[(mb + fr + 8) * SST + kb + fc];
                float a2 = Ab[(mb + fr)     * SST + kb + fc + 4];
                float a3 = Ab[(mb + fr + 8) * SST + kb + fc + 4];
                uint32_t ah[4], al[4];
                tf32_split(a0, ah[0], al[0]);
                tf32_split(a1, ah[1], al[1]);
                tf32_split(a2, ah[2], al[2]);
                tf32_split(a3, ah[3], al[3]);

#pragma unroll
                for (int j = 0; j < 4; j++) {
                    mma_tf32(acc[i][j][0], acc[i][j][1], acc[i][j][2], acc[i][j][3],
                             ah[0], ah[1], ah[2], ah[3], bh[j][0], bh[j][1]);
                    mma_tf32(acc[i][j][0], acc[i][j][1], acc[i][j][2], acc[i][j][3],
                             ah[0], ah[1], ah[2], ah[3], bl[j][0], bl[j][1]);
                    mma_tf32(acc[i][j][0], acc[i][j][1], acc[i][j][2], acc[i][j][3],
                             al[0], al[1], al[2], al[3], bh[j][0], bh[j][1]);
                }
            }
        }
        __syncthreads();
    }

#pragma unroll
    for (int j = 0; j < 4; j++) {
        const int ncol = n0 + warp_n + j * 8 + fc * 2;
        const float2 bv = *reinterpret_cast<const float2*>(&bias[ncol]);
#pragma unroll
        for (int i = 0; i < 4; i++) {
            const int r0 = m0 + warp_m + i * 16 + fr;
            float2 v0, v1;
            v0.x = acc[i][j][0] + bv.x; v0.y = acc[i][j][1] + bv.y;
            v1.x = acc[i][j][2] + bv.x; v1.y = acc[i][j][3] + bv.y;
            *reinterpret_cast<float2*>(&C[(size_t)r0 * ldc + ncol])       = v0;
            *reinterpret_cast<float2*>(&C[(size_t)(r0 + 8) * ldc + ncol]) = v1;
        }
    }
}

// ===========================================================================
// Hierarchical grid barrier:
//  - every block: one st.release to its own flag (no contention)
//  - ONLY block 0 polls the 128 flags (one thread per flag)
//  - block 0 broadcasts via one release store to g_gen
//  - other blocks: single thread spins on the one shared word g_gen
// ===========================================================================
__device__ __forceinline__ void grid_barrier_h(unsigned seq)
{
    __syncthreads();
    if (blockIdx.x == 0) {
        if (threadIdx.x > 0 && threadIdx.x < RNN_BLOCKS) {
            unsigned v;
            do {
                asm volatile("ld.acquire.gpu.global.u32 %0, [%1];"
                             : "=r"(v) : "l"(&g_flags[threadIdx.x]));
            } while (v < seq);
        }
        __syncthreads();
        if (threadIdx.x == 0) {
            asm volatile("st.release.gpu.global.u32 [%0], %1;"
                         :: "l"(&g_gen), "r"(seq));
        }
    } else {
        if (threadIdx.x == 0) {
            asm volatile("st.release.gpu.global.u32 [%0], %1;"
                         :: "l"(&g_flags[blockIdx.x]), "r"(seq));
            unsigned v;
            do {
                asm volatile("ld.acquire.gpu.global.u32 %0, [%1];"
                             : "=r"(v) : "l"(&g_gen));
            } while (v < seq);
        }
        __syncthreads();
    }
}

// legacy atomic barrier on separate vars (used once at scan end for reset)
__device__ __forceinline__ void grid_barrier_atomic()
{
    __syncthreads();
    if (threadIdx.x == 0) {
        unsigned gen;
        asm volatile("ld.acquire.gpu.global.u32 %0, [%1];"
                     : "=r"(gen) : "l"(&g_gen2));
        unsigned old;
        asm volatile("atom.acq_rel.gpu.global.add.u32 %0, [%1], 1;"
                     : "=r"(old) : "l"(&g_cnt));
        if (old == gridDim.x - 1) {
            asm volatile("st.relaxed.gpu.global.u32 [%0], 0;"
                         :: "l"(&g_cnt));
            asm volatile("red.release.gpu.global.add.u32 [%0], 1;"
                         :: "l"(&g_gen2));
        } else {
            unsigned cur;
            do {
                asm volatile("ld.acquire.gpu.global.u32 %0, [%1];"
                             : "=r"(cur) : "l"(&g_gen2));
            } while (cur == gen);
        }
    }
    __syncthreads();
}

// ===========================================================================
// Persistent recurrence (R7 structure, hierarchical barriers, float2 Phase B)
// ===========================================================================
__global__ __launch_bounds__(256) void rnn_scan_k(
    const float* __restrict__ h0, const float* __restrict__ Wi2h)
{
    extern __shared__ float sm[];
    float* sh_hi = sm;                 // [64][SHS]
    float* sh_lo = sm + 64 * SHS;      // [64][SHS]

    const int tid = threadIdx.x;
    const int bid = blockIdx.x;
    const int wid = tid >> 5;
    const int lane = tid & 31;
    const int c   = bid >> 4;
    const int jt  = bid & 15;
    const int j0  = jt * JT;
    const int k0  = c * KC;

    const int mh = wid >> 2;
    const int nw = wid & 3;
    const int fr = lane >> 2;
    const int fc = lane & 3;

    // preload W fragments (loop-invariant)
    uint32_t Wh[2][16][2], Wl[2][16][2];
#pragma unroll
    for (int nj = 0; nj < 2; nj++) {
        const int n = j0 + nw * 16 + nj * 8 + fr;
        const float* wr = &Wi2h[(size_t)n * (NIN + HID) + NIN + k0];
#pragma unroll
        for (int ks = 0; ks < 16; ks++) {
            tf32_split(wr[ks * 8 + fc],     Wh[nj][ks][0], Wl[nj][ks][0]);
            tf32_split(wr[ks * 8 + fc + 4], Wh[nj][ks][1], Wl[nj][ks][1]);
        }
    }

    // Phase B ownership: 512 elements, 2 CONSECUTIVE per thread (float2 paths)
    const int pb_flat = bid * 512 + 2 * tid;
    const int pb_b = pb_flat >> 10;
    const int pb_j = pb_flat & (HID - 1);

    for (int t = 0; t < T_STEPS; t++) {
        // --- stage h(t-1) chunk into smem (split form) ---
        if (t == 0) {
#pragma unroll
            for (int p = 0; p < 8; p++) {
                const int idx4 = tid + p * 256;
                const int b = idx4 >> 5;
                const int kg = (idx4 & 31) * 4;
                float4 v = *reinterpret_cast<const float4*>(&h0[b * HID + k0 + kg]);
                float4 hv, lv;
                split4(v, hv, lv);
                *reinterpret_cast<float4*>(&sh_hi[b * SHS + kg]) = hv;
                *reinterpret_cast<float4*>(&sh_lo[b * SHS + kg]) = lv;
            }
        } else {
#pragma unroll
            for (int p = 0; p < 8; p++) {
                const int idx4 = tid + p * 256;
                const int b = idx4 >> 5;
                const int kg = (idx4 & 31) * 4;
                const int goff = b * HID + k0 + kg;
                float4 hv = __ldcg(reinterpret_cast<const float4*>(&g_Hhi[goff]));
                float4 lv = __ldcg(reinterpret_cast<const float4*>(&g_Hlo[goff]));
                *reinterpret_cast<float4*>(&sh_hi[b * SHS + kg]) = hv;
                *reinterpret_cast<float4*>(&sh_lo[b * SHS + kg]) = lv;
            }
        }
        __syncthreads();

        // --- Phase A: 3xTF32 mma over 16 k8 steps ---
        float acc[2][2][4];
#pragma unroll
        for (int mi = 0; mi < 2; mi++)
#pragma unroll
            for (int nj = 0; nj < 2; nj++)
#pragma unroll
                for (int q = 0; q < 4; q++) acc[mi][nj][q] = 0.0f;

#pragma unroll
        for (int ks = 0; ks < 16; ks++) {
            const int kk = ks * 8 + fc;
            uint32_t ahi[2][4], alo[2][4];
#pragma unroll
            for (int mi = 0; mi < 2; mi++) {
                const int r0 = (mh * 32 + mi * 16 + fr) * SHS;
                const int r8 = r0 + 8 * SHS;
                ahi[mi][0] = __float_as_uint(sh_hi[r0 + kk]);
                ahi[mi][1] = __float_as_uint(sh_hi[r8 + kk]);
                ahi[mi][2] = __float_as_uint(sh_hi[r0 + kk + 4]);
                ahi[mi][3] = __float_as_uint(sh_hi[r8 + kk + 4]);
                alo[mi][0] = __float_as_uint(sh_lo[r0 + kk]);
                alo[mi][1] = __float_as_uint(sh_lo[r8 + kk]);
                alo[mi][2] = __float_as_uint(sh_lo[r0 + kk + 4]);
                alo[mi][3] = __float_as_uint(sh_lo[r8 + kk + 4]);
            }
#pragma unroll
            for (int mi = 0; mi < 2; mi++)
#pragma unroll
                for (int nj = 0; nj < 2; nj++) {
                    mma_tf32(acc[mi][nj][0], acc[mi][nj][1], acc[mi][nj][2], acc[mi][nj][3],
                             ahi[mi][0], ahi[mi][1], ahi[mi][2], ahi[mi][3],
                             Wh[nj][ks][0], Wh[nj][ks][1]);
                    mma_tf32(acc[mi][nj][0], acc[mi][nj][1], acc[mi][nj][2], acc[mi][nj][3],
                             ahi[mi][0], ahi[mi][1], ahi[mi][2], ahi[mi][3],
                             Wl[nj][ks][0], Wl[nj][ks][1]);
                    mma_tf32(acc[mi][nj][0], acc[mi][nj][1], acc[mi][nj][2], acc[mi][nj][3],
                             alo[mi][0], alo[mi][1], alo[mi][2], alo[mi][3],
                             Wh[nj][ks][0], Wh[nj][ks][1]);
                }
        }

        // --- write partials ---
#pragma unroll
        for (int mi = 0; mi < 2; mi++) {
            const int b0 = mh * 32 + mi * 16 + fr;
#pragma unroll
            for (int nj = 0; nj < 2; nj++) {
                const int n = j0 + nw * 16 + nj * 8 + fc * 2;
                float2 v0, v1;
                v0.x = acc[mi][nj][0]; v0.y = acc[mi][nj][1];
                v1.x = acc[mi][nj][2]; v1.y = acc[mi][nj][3];
                __stcg(reinterpret_cast<float2*>(
                    &g_part[(size_t)(c * BSZ + b0) * HID + n]), v0);
                __stcg(reinterpret_cast<float2*>(
                    &g_part[(size_t)(c * BSZ + b0 + 8) * HID + n]), v1);
            }
        }

        // prefetch U (float2) before the barrier
        const size_t u0 = ((size_t)t * BSZ + pb_b) * HID + pb_j;
        float2 uv = __ldcg(reinterpret_cast<const float2*>(&g_UH[u0]));

        grid_barrier_h(2 * t + 1);

        // --- Phase B: reduce + tanh; write h (fp32) + split hi/lo ---
        {
            float v0 = uv.x, v1 = uv.y;
#pragma unroll
            for (int cc = 0; cc < NC; cc++) {
                float2 p = __ldcg(reinterpret_cast<const float2*>(
                    &g_part[(size_t)(cc * BSZ + pb_b) * HID + pb_j]));
                v0 += p.x;
                v1 += p.y;
            }
            v0 = tanhf(v0);
            v1 = tanhf(v1);
            float2 hw; hw.x = v0; hw.y = v1;
            __stcg(reinterpret_cast<float2*>(&g_UH[u0]), hw);
            uint32_t h0b, l0b, h1b, l1b;
            tf32_split(v0, h0b, l0b);
            tf32_split(v1, h1b, l1b);
            float2 hv, lv;
            hv.x = __uint_as_float(h0b); hv.y = __uint_as_float(h1b);
            lv.x = __uint_as_float(l0b); lv.y = __uint_as_float(l1b);
            __stcg(reinterpret_cast<float2*>(&g_Hhi[pb_flat]), hv);
            __stcg(reinterpret_cast<float2*>(&g_Hlo[pb_flat]), lv);
        }

        grid_barrier_h(2 * t + 2);
    }

    // reset barrier state for the next graph replay, behind an atomic barrier
    grid_barrier_atomic();
    if (tid == 0) {
        asm volatile("st.relaxed.gpu.global.u32 [%0], 0;" :: "l"(&g_flags[bid]));
        if (bid == 0)
            asm volatile("st.relaxed.gpu.global.u32 [%0], 0;" :: "l"(&g_gen));
    }
}

// ===========================================================================
extern "C" void kernel_launch(void* const* d_in, const int* in_sizes, int n_in,
                              void* d_out, int out_size)
{
    (void)in_sizes; (void)n_in; (void)out_size;
    const float* x     = (const float*)d_in[0];
    const float* h0    = (const float*)d_in[1];
    const float* W_i2h = (const float*)d_in[2];
    const float* b_i2h = (const float*)d_in[3];
    const float* W_h2o = (const float*)d_in[4];
    const float* b_h2o = (const float*)d_in[5];
    float* out = (float*)d_out;

    float* uh = nullptr;
    cudaGetSymbolAddress((void**)&uh, g_UH);

    // 1) U = X @ Wx^T + b_i2h
    dim3 g1(HID / BN, (T_STEPS * BSZ) / BM);
    gemm_mma_k<<<g1, 256>>>(x, NIN, W_i2h, NIN + HID, b_i2h, uh, HID, NIN);

    // 2) sequential recurrence
    int smem = 2 * 64 * SHS * (int)sizeof(float);
    cudaFuncSetAttribute(rnn_scan_k, cudaFuncAttributeMaxDynamicSharedMemorySize, smem);
    rnn_scan_k<<<RNN_BLOCKS, 256, smem>>>(h0, W_i2h);

    // 3) out = H @ W_h2o^T + b_h2o
    dim3 g3(NOUT / BN, (T_STEPS * BSZ) / BM);
    gemm_mma_k<<<g3, 256>>>(uh, HID, W_h2o, HID, b_h2o, out, NOUT, HID);
}